// round 9
// baseline (speedup 1.0000x reference)
#include <cuda_runtime.h>
#include <cuda_bf16.h>

#define NTH 256
#define VPC 2            // voxels per CTA
#define PPV 32           // points per voxel
#define C1 32            // hidden-1 channels
#define C2 256           // hidden-2 / output channels
#define NEGF (-1e30f)

#define W3T_STRIDE 257   // padded transpose stride -> conflict-free LDS/STS
#define H2S_ELEMS (VPC * PPV * C2)        // 16384 floats
#define W3T_ELEMS (32 * W3T_STRIDE)       // 8224 floats
#define H1S_ELEMS (VPC * PPV * C1)        // 2048 floats
#define PTS_ELEMS (VPC * PPV * 4)         // 256 floats
#define SMEM_FLOATS (H2S_ELEMS + W3T_ELEMS + H1S_ELEMS + PTS_ELEMS)
#define SMEM_BYTES (SMEM_FLOATS * 4)      // 107,648 B -> 2 CTAs/SM

__global__ void __launch_bounds__(NTH, 2)
pointnet_fused(const float* __restrict__ FV,      // [nvox][32][3]
               const int*   __restrict__ FVnum,   // [nvox]
               const float* __restrict__ W1,      // [32][3]
               const float* __restrict__ b1,      // [32]
               const float* __restrict__ W2,      // [256][32]
               const float* __restrict__ b2,      // [256]
               const float* __restrict__ W3,      // [256][256]
               const float* __restrict__ b3,      // [256]
               float* __restrict__ out,           // [nvox][256]
               int nvox)
{
    extern __shared__ float sm[];
    float* h2s = sm;                       // [64 slots][256]  (compacted valid points)
    float* w3t = h2s + H2S_ELEMS;          // [32 kk][257]     (transposed W3 k-tile)
    float* h1s = w3t + W3T_ELEMS;          // [2][32][32]
    float* pts = h1s + H1S_ELEMS;          // [2][32][4]
    __shared__ int s_num[VPC];

    const int tid   = threadIdx.x;
    const int vbase = blockIdx.x * VPC;

    if (tid < VPC) {
        int v = vbase + tid;
        int n = (v < nvox) ? FVnum[v] : 0;
        if (n < 0)  n = 0;
        if (n > PPV) n = PPV;
        s_num[tid] = n;
    }
    __syncthreads();

    const int num0 = s_num[0];
    const int num1 = s_num[1];
    // empty voxel -> 1 zero point, so pooled == pointnet(0) == zfeat exactly
    const int nv0 = (num0 > 0) ? num0 : 1;
    const int nv1 = (num1 > 0) ? num1 : 1;
    const int M   = nv0 + nv1;             // total compacted slots (<= 64)

    // ---- load points (zeroed for empty voxels) ----
    for (int i = tid; i < VPC * PPV * 3; i += NTH) {
        int vx = i / (PPV * 3);
        int r  = i - vx * (PPV * 3);
        int p  = r / 3;
        int num = vx ? num1 : num0;
        float val = 0.f;
        if (num > 0 && (vbase + vx) < nvox)
            val = FV[(size_t)(vbase + vx) * (PPV * 3) + r];
        pts[vx * (PPV * 4) + p * 4 + (r - p * 3)] = val;
    }
    __syncthreads();

    // ---- layer 1: [p,3] -> [p,32], relu ----
    for (int i = tid; i < VPC * PPV * C1; i += NTH) {
        int vx = i >> 10;          // / (32*32)
        int r  = i & 1023;
        int p  = r >> 5;
        int j  = r & 31;
        const float* pp = &pts[vx * (PPV * 4) + p * 4];
        float h = b1[j] + W1[j*3+0]*pp[0] + W1[j*3+1]*pp[1] + W1[j*3+2]*pp[2];
        h1s[i] = fmaxf(h, 0.f);
    }
    __syncthreads();

    // ---- layer 2: thread owns channel o; write compacted valid slots ----
    {
        const int o = tid;
        float4 w2v[8];
        #pragma unroll
        for (int q = 0; q < 8; ++q)
            w2v[q] = *(const float4*)(W2 + o * C1 + 4 * q);
        const float bb = b2[o];
        int slot = 0;
        #pragma unroll
        for (int vx = 0; vx < VPC; ++vx) {
            const int nv = vx ? nv1 : nv0;
            const float* h1p = h1s + vx * (PPV * C1);
            #pragma unroll 1
            for (int p = 0; p < nv; ++p) {
                float a = bb;
                const float4* h4 = (const float4*)(h1p + p * C1);
                #pragma unroll
                for (int q = 0; q < 8; ++q) {
                    float4 h = h4[q];
                    a = fmaf(w2v[q].x, h.x, a);
                    a = fmaf(w2v[q].y, h.y, a);
                    a = fmaf(w2v[q].z, h.z, a);
                    a = fmaf(w2v[q].w, h.w, a);
                }
                h2s[slot * C2 + o] = fmaxf(a, 0.f);
                ++slot;
            }
        }
    }
    // h2s rows >= M are stale garbage: excluded at max phase, never affects output.

    // ---- layer 3: k-tiled, W3 staged transposed in smem, acc[] register-resident ----
    float acc[VPC * PPV];
    #pragma unroll
    for (int s = 0; s < VPC * PPV; ++s) acc[s] = 0.f;

    const int o = tid;
    const int nch = (M + 15) >> 4;   // active 16-point chunks (1..4)

    for (int kt = 0; kt < 8; ++kt) {
        const int k0 = kt * 32;
        __syncthreads();             // protect w3t reuse (iter 0: h2s ready)
        // stage W3[:, k0:k0+32] transposed: coalesced LDG.128, conflict-free STS
        #pragma unroll
        for (int r = 0; r < 8; ++r) {
            int idx = tid + NTH * r;          // 0..2047
            int oo  = idx >> 3;               // 0..255
            int q   = idx & 7;                // 0..7
            float4 g = *(const float4*)(W3 + oo * C2 + k0 + 4 * q);
            w3t[(4*q+0) * W3T_STRIDE + oo] = g.x;
            w3t[(4*q+1) * W3T_STRIDE + oo] = g.y;
            w3t[(4*q+2) * W3T_STRIDE + oo] = g.z;
            w3t[(4*q+3) * W3T_STRIDE + oo] = g.w;
        }
        __syncthreads();

        #pragma unroll
        for (int ch = 0; ch < 4; ++ch) {
            if (ch < nch) {                    // uniform across block: no divergence
                #pragma unroll
                for (int k4 = 0; k4 < 8; ++k4) {
                    // per-thread weights, conflict-free scalar LDS
                    float w0 = w3t[(4*k4+0) * W3T_STRIDE + o];
                    float w1 = w3t[(4*k4+1) * W3T_STRIDE + o];
                    float w2s = w3t[(4*k4+2) * W3T_STRIDE + o];
                    float w3s = w3t[(4*k4+3) * W3T_STRIDE + o];
                    #pragma unroll
                    for (int pi = 0; pi < 16; ++pi) {
                        const int s = ch * 16 + pi;            // static reg index
                        float4 h = *(const float4*)(h2s + s * C2 + k0 + 4 * k4); // broadcast LDS.128
                        float t = fmaf(w0,  h.x, acc[s]);
                        t       = fmaf(w1,  h.y, t);
                        t       = fmaf(w2s, h.z, t);
                        acc[s]  = fmaf(w3s, h.w, t);
                    }
                }
            }
        }
    }

    // ---- max-pool per voxel (b3 added post-max: max commutes with +const) ----
    float m0 = NEGF, m1 = NEGF;
    #pragma unroll
    for (int s = 0; s < VPC * PPV; ++s) {
        float v = acc[s];
        if (s < nv0)     m0 = fmaxf(m0, v);
        else if (s < M)  m1 = fmaxf(m1, v);
    }
    const float bo = b3[o];
    if (vbase     < nvox) out[(size_t)(vbase    ) * C2 + o] = m0 + bo;
    if (vbase + 1 < nvox) out[(size_t)(vbase + 1) * C2 + o] = m1 + bo;
}

extern "C" void kernel_launch(void* const* d_in, const int* in_sizes, int n_in,
                              void* d_out, int out_size)
{
    const float* FV    = (const float*)d_in[0];
    const int*   FVnum = (const int*)  d_in[1];
    const float* W1    = (const float*)d_in[2];
    const float* b1    = (const float*)d_in[3];
    const float* W2    = (const float*)d_in[4];
    const float* b2    = (const float*)d_in[5];
    const float* W3    = (const float*)d_in[6];
    const float* b3    = (const float*)d_in[7];
    float* out = (float*)d_out;

    const int nvox = in_sizes[1];                 // B*H*W = 18432
    const int grid = (nvox + VPC - 1) / VPC;      // 9216 CTAs

    cudaFuncSetAttribute(pointnet_fused,
                         cudaFuncAttributeMaxDynamicSharedMemorySize, SMEM_BYTES);
    pointnet_fused<<<grid, NTH, SMEM_BYTES>>>(FV, FVnum, W1, b1, W2, b2, W3, b3,
                                              out, nvox);
}

// round 11
// speedup vs baseline: 1.2728x; 1.2728x over previous
#include <cuda_runtime.h>

#define NTH 256
#define VPC 2            // voxels per CTA
#define PPV 32           // points per voxel
#define C1 32            // hidden-1 channels
#define C2 256           // hidden-2 / output channels
#define NEGF (-1e30f)

#define H2S_STRIDE 256   // h2 rows; reads are warp-uniform -> no pad needed
#define W3T_STRIDE 258   // even stride: 8B-aligned rows for LDS.64, conflict-free pair loads
#define H2S_ELEMS (64 * H2S_STRIDE)       // 16384 floats
#define W3T_ELEMS (32 * W3T_STRIDE)       // 8256 floats
#define H1S_ELEMS (VPC * PPV * C1)        // 2048 floats
#define PTS_ELEMS (VPC * PPV * 4)         // 256 floats
#define SMEM_FLOATS (H2S_ELEMS + W3T_ELEMS + H1S_ELEMS + PTS_ELEMS)
#define SMEM_BYTES (SMEM_FLOATS * 4)      // 107,776 B -> 2 CTAs/SM

typedef unsigned long long u64;

// packed fp32x2 helpers (SASS FFMA2 path; PTX-only pattern)
__device__ __forceinline__ u64 pack2(float x) {
    u64 r; asm("mov.b64 %0, {%1, %1};" : "=l"(r) : "r"(__float_as_uint(x))); return r;
}
__device__ __forceinline__ void ffma2(u64& acc, u64 a, u64 b) {
    asm("fma.rn.f32x2 %0, %1, %2, %0;" : "+l"(acc) : "l"(a), "l"(b));
}
__device__ __forceinline__ void unpack2(u64 v, float& lo, float& hi) {
    unsigned int a, b; asm("mov.b64 {%0, %1}, %2;" : "=r"(a), "=r"(b) : "l"(v));
    lo = __uint_as_float(a); hi = __uint_as_float(b);
}

__global__ void __launch_bounds__(NTH, 2)
pointnet_fused(const float* __restrict__ FV,      // [nvox][32][3]
               const int*   __restrict__ FVnum,   // [nvox]
               const float* __restrict__ W1,      // [32][3]
               const float* __restrict__ b1,      // [32]
               const float* __restrict__ W2,      // [256][32]
               const float* __restrict__ b2,      // [256]
               const float* __restrict__ W3,      // [256][256]
               const float* __restrict__ b3,      // [256]
               float* __restrict__ out,           // [nvox][256]
               int nvox)
{
    extern __shared__ float sm[];
    float* h2s = sm;                       // [64 slots][256]  fp32 features
    float* w3t = h2s + H2S_ELEMS;          // [32 kk][258]     W3 k-tile, [k][o]
    float* h1s = w3t + W3T_ELEMS;          // [2][32][32]
    float* pts = h1s + H1S_ELEMS;          // [2][32][4]
    __shared__ int s_num[VPC];

    const int tid   = threadIdx.x;
    const int vbase = blockIdx.x * VPC;

    if (tid < VPC) {
        int v = vbase + tid;
        int n = (v < nvox) ? FVnum[v] : 0;
        if (n < 0)  n = 0;
        if (n > PPV) n = PPV;
        s_num[tid] = n;
    }
    __syncthreads();

    const int num0 = s_num[0];
    const int num1 = s_num[1];
    // empty voxel -> 1 zero point, so pooled == pointnet(0) == zfeat exactly
    const int nv0 = (num0 > 0) ? num0 : 1;
    const int nv1 = (num1 > 0) ? num1 : 1;
    const int M   = nv0 + nv1;             // compacted slots (2..64)

    // ---- load points (zeroed for empty voxels) ----
    for (int i = tid; i < VPC * PPV * 3; i += NTH) {
        int vx = i / (PPV * 3);
        int r  = i - vx * (PPV * 3);
        int p  = r / 3;
        int num = vx ? num1 : num0;
        float val = 0.f;
        if (num > 0 && (vbase + vx) < nvox)
            val = FV[(size_t)(vbase + vx) * (PPV * 3) + r];
        pts[vx * (PPV * 4) + p * 4 + (r - p * 3)] = val;
    }
    __syncthreads();

    // ---- layer 1: [p,3] -> [p,32], relu ----
    for (int i = tid; i < VPC * PPV * C1; i += NTH) {
        int vx = i >> 10;
        int r  = i & 1023;
        int p  = r >> 5;
        int j  = r & 31;
        const float* pp = &pts[vx * (PPV * 4) + p * 4];
        float h = b1[j] + W1[j*3+0]*pp[0] + W1[j*3+1]*pp[1] + W1[j*3+2]*pp[2];
        h1s[i] = fmaxf(h, 0.f);
    }
    __syncthreads();

    // ---- layer 2: thread owns channel o; write compacted valid slots ----
    {
        const int o = tid;
        float4 w2v[8];
        #pragma unroll
        for (int q = 0; q < 8; ++q)
            w2v[q] = *(const float4*)(W2 + o * C1 + 4 * q);
        const float bb = b2[o];
        int slot = 0;
        #pragma unroll
        for (int vx = 0; vx < VPC; ++vx) {
            const int nv = vx ? nv1 : nv0;
            const float* h1p = h1s + vx * (PPV * C1);
            #pragma unroll 1
            for (int p = 0; p < nv; ++p) {
                float a = bb;
                const float4* h4 = (const float4*)(h1p + p * C1);
                #pragma unroll
                for (int q = 0; q < 8; ++q) {
                    float4 h = h4[q];
                    a = fmaf(w2v[q].x, h.x, a);
                    a = fmaf(w2v[q].y, h.y, a);
                    a = fmaf(w2v[q].z, h.z, a);
                    a = fmaf(w2v[q].w, h.w, a);
                }
                h2s[slot * H2S_STRIDE + o] = fmaxf(a, 0.f);   // lanes consecutive o -> conflict-free
                ++slot;
            }
        }
    }
    // h2s rows >= M are stale garbage: only pollute slots excluded at pooling.

    // ---- layer 3: 8s x 8o register tile per thread, packed f32x2 FMAs ----
    // warp sg owns slots [8sg, 8sg+8); lane og owns o = {64j + 2og + h : j=0..3, h=0..1}
    u64 acc2[32];
    #pragma unroll
    for (int i = 0; i < 32; ++i) acc2[i] = 0ull;

    const int og = tid & 31;
    const int sg = tid >> 5;
    const bool wactive = (sg * 8) < M;      // warp-uniform pruning
    const int obase = 2 * og;

    for (int kt = 0; kt < 8; ++kt) {
        const int k0 = kt * 32;
        __syncthreads();             // protect w3t reuse (iter 0: h2s ready)
        // stage W3[:, k0:k0+32] transposed -> w3t[kk][o]; coalesced LDG.128
        #pragma unroll
        for (int r = 0; r < 8; ++r) {
            int idx = tid + NTH * r;          // 0..2047
            int oo  = idx >> 3;               // 0..255
            int q   = idx & 7;                // 0..7
            float4 g = *(const float4*)(W3 + oo * C2 + k0 + 4 * q);
            w3t[(4*q+0) * W3T_STRIDE + oo] = g.x;
            w3t[(4*q+1) * W3T_STRIDE + oo] = g.y;
            w3t[(4*q+2) * W3T_STRIDE + oo] = g.z;
            w3t[(4*q+3) * W3T_STRIDE + oo] = g.w;
        }
        __syncthreads();

        if (wactive) {
            const float* hbase = h2s + sg * 8 * H2S_STRIDE + k0;
            #pragma unroll 2
            for (int kk = 0; kk < 32; ++kk) {
                u64 wp[4];
                const float* wrow = w3t + kk * W3T_STRIDE + obase;
                #pragma unroll
                for (int j = 0; j < 4; ++j)
                    wp[j] = *(const u64*)(wrow + 64 * j);   // LDS.64, lanes cover 64 consec floats
                #pragma unroll
                for (int p = 0; p < 8; ++p) {
                    u64 hh = pack2(hbase[p * H2S_STRIDE + kk]);  // warp-uniform scalar LDS
                    #pragma unroll
                    for (int j = 0; j < 4; ++j)
                        ffma2(acc2[j * 8 + p], wp[j], hh);
                }
            }
        }
    }

    // ---- max-pool: per-thread partials -> pmax (aliased on dead w3t) -> final ----
    __syncthreads();                 // all compute done; safe to overwrite w3t
    float* pmax = w3t;               // [8 sg][2 vox][256 o]

    float m0[8], m1[8];              // index q = j*2 + h
    #pragma unroll
    for (int q = 0; q < 8; ++q) { m0[q] = NEGF; m1[q] = NEGF; }
    #pragma unroll
    for (int p = 0; p < 8; ++p) {
        const int slot = sg * 8 + p;
        const bool v0 = slot < nv0;
        const bool v1 = (slot >= nv0) && (slot < M);
        #pragma unroll
        for (int j = 0; j < 4; ++j) {
            float lo, hi; unpack2(acc2[j * 8 + p], lo, hi);
            if (v0) { m0[j*2]   = fmaxf(m0[j*2],   lo);
                      m0[j*2+1] = fmaxf(m0[j*2+1], hi); }
            if (v1) { m1[j*2]   = fmaxf(m1[j*2],   lo);
                      m1[j*2+1] = fmaxf(m1[j*2+1], hi); }
        }
    }
    #pragma unroll
    for (int j = 0; j < 4; ++j) {
        const int o = j * 64 + obase;                    // even -> 8B aligned
        *(float2*)&pmax[sg * 512 +       o] = make_float2(m0[j*2], m0[j*2+1]);
        *(float2*)&pmax[sg * 512 + 256 + o] = make_float2(m1[j*2], m1[j*2+1]);
    }
    __syncthreads();

    {
        const int o = tid;
        float r0 = NEGF, r1 = NEGF;
        #pragma unroll
        for (int s8 = 0; s8 < 8; ++s8) {
            r0 = fmaxf(r0, pmax[s8 * 512 +       o]);
            r1 = fmaxf(r1, pmax[s8 * 512 + 256 + o]);
        }
        const float bo = b3[o];
        if (vbase     < nvox) out[(size_t)(vbase    ) * C2 + o] = r0 + bo;
        if (vbase + 1 < nvox) out[(size_t)(vbase + 1) * C2 + o] = r1 + bo;
    }
}

extern "C" void kernel_launch(void* const* d_in, const int* in_sizes, int n_in,
                              void* d_out, int out_size)
{
    const float* FV    = (const float*)d_in[0];
    const int*   FVnum = (const int*)  d_in[1];
    const float* W1    = (const float*)d_in[2];
    const float* b1    = (const float*)d_in[3];
    const float* W2    = (const float*)d_in[4];
    const float* b2    = (const float*)d_in[5];
    const float* W3    = (const float*)d_in[6];
    const float* b3    = (const float*)d_in[7];
    float* out = (float*)d_out;

    const int nvox = in_sizes[1];                 // B*H*W = 18432
    const int grid = (nvox + VPC - 1) / VPC;      // 9216 CTAs

    cudaFuncSetAttribute(pointnet_fused,
                         cudaFuncAttributeMaxDynamicSharedMemorySize, SMEM_BYTES);
    pointnet_fused<<<grid, NTH, SMEM_BYTES>>>(FV, FVnum, W1, b1, W2, b2, W3, b3,
                                              out, nvox);
}